// round 6
// baseline (speedup 1.0000x reference)
#include <cuda_runtime.h>

#define BB 8
#define CIN 64
#define COUT 64
#define HH 128
#define WW 128
#define HW (HH*WW)
#define KK 9

typedef unsigned long long u64;

// packed f32x2 FMA: one FFMA2 SASS inst (2 fp32 FMAs, rt=2/SMSP like FFMA)
#define FMA2(d, a, b, c) \
    asm("fma.rn.f32x2 %0, %1, %2, %3;" : "=l"(d) : "l"(a), "l"(b), "l"(c))
#define DUP2(d, s) \
    asm("mov.b64 %0, {%1, %1};" : "=l"(d) : "r"(__float_as_uint(s)))
#define UNPK2(lo, hi, v) \
    asm("mov.b64 {%0, %1}, %2;" : "=f"(lo), "=f"(hi) : "l"(v))

// ---------------- scratch (no allocations allowed) ----------------
__device__ float g_offset[BB*18*HW];   // [b][2k+{dy,dx}][h][w]
__device__ float g_mask[BB*9*HW];      // [b][k][h][w]
__device__ float g_sum[COUT];
__device__ float g_sumsq[COUT];
__device__ float g_scale[COUT];
__device__ float g_shift[COUT];

// ---------------- kernel 0: zero stats ----------------
__global__ void k_zero() {
    int t = threadIdx.x;
    if (t < COUT) { g_sum[t] = 0.f; g_sumsq[t] = 0.f; }
}

// ---------------- kernel 1: offset (18ch) + mask (9ch) 3x3 conv, fused ----------------
// grid (8,8,8)=(tx,ty,b), block 256 = 16x16 pixels
#define SMEM1_FLOATS (CIN*KK*28 + 18*20)
__global__ __launch_bounds__(256) void k_offmask(
    const float* __restrict__ x,
    const float* __restrict__ off_w, const float* __restrict__ off_b,
    const float* __restrict__ mod_w, const float* __restrict__ mod_b)
{
    extern __shared__ float sm[];
    float* wsm = sm;                  // [c][k][28] (27 outputs + 1 zero pad)
    float* xs  = sm + CIN*KK*28;      // [18][20]

    const int tid = threadIdx.x;
    const int b = blockIdx.z;
    const int ty = tid >> 4, tx = tid & 15;
    const int gy = blockIdx.y*16 + ty;
    const int gx = blockIdx.x*16 + tx;

    // stage weights: wsm[(c*9+k)*28 + o], o==27 pad = 0
    for (int idx = tid; idx < 28*CIN*KK; idx += 256) {
        int o = idx / (CIN*KK);
        int rem = idx - o*(CIN*KK);
        int c = rem / KK, k = rem - c*KK;
        float v = 0.f;
        if (o < 18)      v = off_w[(o*CIN + c)*KK + k];
        else if (o < 27) v = mod_w[((o-18)*CIN + c)*KK + k];
        wsm[(c*KK + k)*28 + o] = v;
    }

    u64 acc2[14];
#pragma unroll
    for (int p = 0; p < 14; p++) acc2[p] = 0ull;

    const int gy0 = blockIdx.y*16 - 1;
    const int gx0 = blockIdx.x*16 - 1;

    for (int c = 0; c < CIN; c++) {
        __syncthreads();   // protect xs overwrite (and weight staging on iter 0)
        const float* xp = x + (size_t)(b*CIN + c)*HW;
        for (int idx = tid; idx < 18*18; idx += 256) {
            int r = idx / 18, cc = idx - r*18;
            int yy = gy0 + r, xx = gx0 + cc;
            float v = 0.f;
            if (yy >= 0 && yy < HH && xx >= 0 && xx < WW) v = xp[yy*WW + xx];
            xs[r*20 + cc] = v;
        }
        __syncthreads();
        float xv[9];
#pragma unroll
        for (int k = 0; k < 9; k++)
            xv[k] = xs[(ty + k/3)*20 + (tx + (k - (k/3)*3))];
#pragma unroll
        for (int k = 0; k < 9; k++) {
            const ulonglong2* wr = (const ulonglong2*)&wsm[(c*KK + k)*28];
            u64 wp[14];
#pragma unroll
            for (int q = 0; q < 7; q++) {
                ulonglong2 t = wr[q];
                wp[2*q] = t.x; wp[2*q+1] = t.y;
            }
            u64 xk2; DUP2(xk2, xv[k]);
#pragma unroll
            for (int p = 0; p < 14; p++) FMA2(acc2[p], xk2, wp[p], acc2[p]);
        }
    }

    float acc[28];
#pragma unroll
    for (int p = 0; p < 14; p++) UNPK2(acc[2*p], acc[2*p+1], acc2[p]);

    const int pix = gy*WW + gx;
#pragma unroll
    for (int o = 0; o < 18; o++)
        g_offset[(b*18 + o)*HW + pix] = acc[o] + off_b[o];
#pragma unroll
    for (int o = 0; o < 9; o++) {
        float t = acc[18 + o] + mod_b[o];
        g_mask[(b*9 + o)*HW + pix] = 2.f / (1.f + expf(-t));
    }
}

// ---------------- kernel 2: deform sample + einsum + BN partial sums ----------------
// grid (128 rows, 8 batch), block 512. One block = one output row (128 px, all 64 out ch).
#define SMEM2_FLOATS (COUT*576 + 2*9*128)
__global__ __launch_bounds__(512) void k_deform(
    const float* __restrict__ x,
    const float* __restrict__ w,
    const float* __restrict__ bias,
    float* __restrict__ out)
{
    extern __shared__ float sm[];
    float* Wsm = sm;                 // [o][576]  natural layout (broadcast LDS)
    float* vsm = sm + COUT*576;      // [2][9][128]

    const int tid  = threadIdx.x;
    const int y    = blockIdx.x;
    const int b    = blockIdx.y;
    const int warp = tid >> 5, lane = tid & 31;
    const int obase = warp * 4;      // 16 warps x 4 = 64 out channels
    const int pbase = lane * 4;      // 32 lanes x 4 = 128 pixels

    // stage W coalesced
    {
        const float4* src = (const float4*)w;
        float4* dst = (float4*)Wsm;
        for (int i = tid; i < COUT*576/4; i += 512) dst[i] = src[i];
    }

    // precompute my bilinear samples (channel-independent)
    int   sidx[3][4];
    float swt[3][4];
    int   sk[3], spx[3];
    bool  sval[3];
#pragma unroll
    for (int i = 0; i < 3; i++) {
        int sid = tid + 512*i;
        sval[i] = (sid < 1152);
        int k  = sval[i] ? (sid >> 7) : 0;
        int px = sid & 127;
        sk[i] = k; spx[i] = px;
        float dy = g_offset[(b*18 + 2*k  )*HW + y*WW + px];
        float dx = g_offset[(b*18 + 2*k+1)*HW + y*WW + px];
        float m  = g_mask  [(b*9  + k    )*HW + y*WW + px];
        if (!sval[i]) m = 0.f;
        float py  = dy + (float)(k/3 - 1) + (float)y;
        float pxf = dx + (float)(k - (k/3)*3 - 1) + (float)px;
        float fy = floorf(py), fx = floorf(pxf);
        float ly = py - fy, lx = pxf - fx;
        int y0 = (int)fy, x0 = (int)fx;
        int y1 = y0 + 1,  x1 = x0 + 1;
        float cw[4] = { (1.f-ly)*(1.f-lx)*m, (1.f-ly)*lx*m,
                        ly*(1.f-lx)*m,       ly*lx*m };
        int cy[4] = { y0, y0, y1, y1 };
        int cx[4] = { x0, x1, x0, x1 };
#pragma unroll
        for (int j = 0; j < 4; j++) {
            bool v = (cy[j] >= 0 && cy[j] < HH && cx[j] >= 0 && cx[j] < WW);
            int yc = min(max(cy[j], 0), HH-1);
            int xc = min(max(cx[j], 0), WW-1);
            sidx[i][j] = yc*WW + xc;
            swt[i][j]  = v ? cw[j] : 0.f;
        }
    }

    const float* xb = x + (size_t)b*CIN*HW;

    // gather c=0
    float gv[3][4];
#pragma unroll
    for (int i = 0; i < 3; i++)
#pragma unroll
        for (int j = 0; j < 4; j++) gv[i][j] = xb[sidx[i][j]];

    __syncthreads();   // W staged
#pragma unroll
    for (int i = 0; i < 3; i++) if (sval[i]) {
        float v = gv[i][0]*swt[i][0] + gv[i][1]*swt[i][1]
                + gv[i][2]*swt[i][2] + gv[i][3]*swt[i][3];
        vsm[(0*9 + sk[i])*128 + spx[i]] = v;
    }
    __syncthreads();

    u64 acc2[4][2];   // [oi][px pair]  (packed f32x2)
#pragma unroll
    for (int oi = 0; oi < 4; oi++) { acc2[oi][0] = 0ull; acc2[oi][1] = 0ull; }

    for (int c = 0; c < CIN; c++) {
        const int cur = c & 1, nxt = cur ^ 1;

        // issue gather loads for c+1 early (hidden under compute)
        if (c + 1 < CIN) {
            const float* xp = xb + (c+1)*HW;
#pragma unroll
            for (int i = 0; i < 3; i++)
#pragma unroll
                for (int j = 0; j < 4; j++) gv[i][j] = xp[sidx[i][j]];
        }

        // compute: acc[o][px] += v[k][px] * W[o][c*9+k]   (2 px per FFMA2)
        ulonglong2 v2[9];
#pragma unroll
        for (int k = 0; k < 9; k++)
            v2[k] = *(const ulonglong2*)&vsm[(cur*9 + k)*128 + pbase];
#pragma unroll
        for (int oi = 0; oi < 4; oi++) {
            const float* wr = &Wsm[(obase + oi)*576 + c*9];
#pragma unroll
            for (int k = 0; k < 9; k++) {
                u64 wp; DUP2(wp, wr[k]);
                FMA2(acc2[oi][0], v2[k].x, wp, acc2[oi][0]);
                FMA2(acc2[oi][1], v2[k].y, wp, acc2[oi][1]);
            }
        }

        if (c + 1 < CIN) {
#pragma unroll
            for (int i = 0; i < 3; i++) if (sval[i]) {
                float v = gv[i][0]*swt[i][0] + gv[i][1]*swt[i][1]
                        + gv[i][2]*swt[i][2] + gv[i][3]*swt[i][3];
                vsm[(nxt*9 + sk[i])*128 + spx[i]] = v;
            }
        }
        __syncthreads();
    }

    // epilogue: bias, write y, per-channel partial sums
#pragma unroll
    for (int oi = 0; oi < 4; oi++) {
        int o = obase + oi;
        float bb = bias[o];
        float a0, a1, a2, a3;
        UNPK2(a0, a1, acc2[oi][0]);
        UNPK2(a2, a3, acc2[oi][1]);
        float4 r;
        r.x = a0 + bb; r.y = a1 + bb;
        r.z = a2 + bb; r.w = a3 + bb;
        *(float4*)&out[(size_t)(b*COUT + o)*HW + y*WW + pbase] = r;

        float s  = r.x + r.y + r.z + r.w;
        float ss = r.x*r.x + r.y*r.y + r.z*r.z + r.w*r.w;
#pragma unroll
        for (int d = 16; d; d >>= 1) {
            s  += __shfl_xor_sync(0xffffffffu, s,  d);
            ss += __shfl_xor_sync(0xffffffffu, ss, d);
        }
        if (lane == 0) {
            atomicAdd(&g_sum[o], s);
            atomicAdd(&g_sumsq[o], ss);
        }
    }
}

// ---------------- kernel 3: BN finalize ----------------
__global__ void k_bnstats(const float* __restrict__ gamma, const float* __restrict__ beta) {
    int o = threadIdx.x;
    if (o < COUT) {
        const float n = (float)(BB*HW);
        float mean = g_sum[o] / n;
        float var  = g_sumsq[o] / n - mean*mean;
        var = fmaxf(var, 0.f);
        float sc = gamma[o] / sqrtf(var + 1e-5f);
        g_scale[o] = sc;
        g_shift[o] = beta[o] - mean*sc;
    }
}

// ---------------- kernel 4: normalize + relu, in place ----------------
__global__ void k_apply(float* __restrict__ out) {
    int i = blockIdx.x*blockDim.x + threadIdx.x;   // float4 index
    const int total = BB*COUT*HW/4;
    if (i < total) {
        int o = (i >> 12) & 63;   // 4096 float4 per channel plane
        float sc = g_scale[o], sh = g_shift[o];
        float4 v = ((float4*)out)[i];
        v.x = fmaxf(fmaf(v.x, sc, sh), 0.f);
        v.y = fmaxf(fmaf(v.y, sc, sh), 0.f);
        v.z = fmaxf(fmaf(v.z, sc, sh), 0.f);
        v.w = fmaxf(fmaf(v.w, sc, sh), 0.f);
        ((float4*)out)[i] = v;
    }
}

// ---------------- launcher ----------------
extern "C" void kernel_launch(void* const* d_in, const int* in_sizes, int n_in,
                              void* d_out, int out_size)
{
    const float* x     = (const float*)d_in[0];
    const float* off_w = (const float*)d_in[1];
    const float* off_b = (const float*)d_in[2];
    const float* mod_w = (const float*)d_in[3];
    const float* mod_b = (const float*)d_in[4];
    const float* w     = (const float*)d_in[5];
    const float* bias  = (const float*)d_in[6];
    const float* gamma = (const float*)d_in[7];
    const float* beta  = (const float*)d_in[8];
    float* out = (float*)d_out;

    const int smem1 = SMEM1_FLOATS * 4;
    const int smem2 = SMEM2_FLOATS * 4;
    cudaFuncSetAttribute(k_offmask, cudaFuncAttributeMaxDynamicSharedMemorySize, smem1);
    cudaFuncSetAttribute(k_deform,  cudaFuncAttributeMaxDynamicSharedMemorySize, smem2);

    k_zero<<<1, 64>>>();
    k_offmask<<<dim3(8,8,8), 256, smem1>>>(x, off_w, off_b, mod_w, mod_b);
    k_deform<<<dim3(128,8), 512, smem2>>>(x, w, bias, out);
    k_bnstats<<<1, 64>>>(gamma, beta);
    k_apply<<<8192, 256>>>(out);
}

// round 7
// speedup vs baseline: 1.1353x; 1.1353x over previous
#include <cuda_runtime.h>

#define BB 8
#define CIN 64
#define COUT 64
#define HH 128
#define WW 128
#define HW (HH*WW)
#define KK 9

typedef unsigned long long u64;

// packed f32x2 FMA: one FFMA2 SASS inst (2 fp32 FMAs, rt=2/SMSP like FFMA)
#define FMA2(d, a, b, c) \
    asm("fma.rn.f32x2 %0, %1, %2, %3;" : "=l"(d) : "l"(a), "l"(b), "l"(c))
#define DUP2(d, s) \
    asm("mov.b64 %0, {%1, %1};" : "=l"(d) : "r"(__float_as_uint(s)))
#define UNPK2(lo, hi, v) \
    asm("mov.b64 {%0, %1}, %2;" : "=f"(lo), "=f"(hi) : "l"(v))

// ---------------- scratch (no allocations allowed) ----------------
__device__ float g_offset[BB*18*HW];   // [b][2k+{dy,dx}][h][w]
__device__ float g_mask[BB*9*HW];      // [b][k][h][w]
__device__ float g_Wt[576*COUT];       // transposed deform weights [c*9+k][o]
__device__ float g_sum[COUT];
__device__ float g_sumsq[COUT];
__device__ float g_scale[COUT];
__device__ float g_shift[COUT];

// ---------------- kernel 0: zero stats ----------------
__global__ void k_zero() {
    int t = threadIdx.x;
    if (t < COUT) { g_sum[t] = 0.f; g_sumsq[t] = 0.f; }
}

// ---------------- kernel 0b: transpose W -> g_Wt[ck][o] ----------------
__global__ void k_wprep(const float* __restrict__ w) {
    int i = blockIdx.x*256 + threadIdx.x;
    if (i < COUT*576) {
        int o = i / 576, ck = i - o*576;
        g_Wt[ck*COUT + o] = w[i];
    }
}

// ---------------- kernel 1: offset (18ch) + mask (9ch) 3x3 conv, fused ----
// grid (4,8,8), block 256 = 16x16 threads, each thread 2 px (cols tx, tx+16)
#define SMEM1_FLOATS (CIN*KK*28 + 18*36)
__global__ __launch_bounds__(256) void k_offmask(
    const float* __restrict__ x,
    const float* __restrict__ off_w, const float* __restrict__ off_b,
    const float* __restrict__ mod_w, const float* __restrict__ mod_b)
{
    extern __shared__ float sm[];
    float* wsm = sm;                  // [c*9+k][28] (27 outputs + 1 zero pad)
    float* xs  = sm + CIN*KK*28;      // [18][36] (34 used cols)

    const int tid = threadIdx.x;
    const int b = blockIdx.z;
    const int ty = tid >> 4, tx = tid & 15;
    const int gy  = blockIdx.y*16 + ty;
    const int gxA = blockIdx.x*32 + tx;
    const int gxB = gxA + 16;

    // stage weights: wsm[(c*9+k)*28 + o], o==27 pad = 0
    for (int idx = tid; idx < 28*CIN*KK; idx += 256) {
        int o = idx / (CIN*KK);
        int rem = idx - o*(CIN*KK);
        int c = rem / KK, k = rem - c*KK;
        float v = 0.f;
        if (o < 18)      v = off_w[(o*CIN + c)*KK + k];
        else if (o < 27) v = mod_w[((o-18)*CIN + c)*KK + k];
        wsm[(c*KK + k)*28 + o] = v;
    }

    u64 accA[14], accB[14];
#pragma unroll
    for (int p = 0; p < 14; p++) { accA[p] = 0ull; accB[p] = 0ull; }

    const int gy0 = blockIdx.y*16 - 1;
    const int gx0 = blockIdx.x*32 - 1;

    for (int c = 0; c < CIN; c++) {
        __syncthreads();   // protect xs overwrite (and weight staging on iter 0)
        const float* xp = x + (size_t)(b*CIN + c)*HW;
        for (int idx = tid; idx < 18*34; idx += 256) {
            int r = idx / 34, cc = idx - r*34;
            int yy = gy0 + r, xx = gx0 + cc;
            float v = 0.f;
            if (yy >= 0 && yy < HH && xx >= 0 && xx < WW) v = xp[yy*WW + xx];
            xs[r*36 + cc] = v;
        }
        __syncthreads();
        float xA[9], xB[9];
#pragma unroll
        for (int k = 0; k < 9; k++) {
            int r = k/3, s = k - r*3;
            xA[k] = xs[(ty + r)*36 + tx + s];
            xB[k] = xs[(ty + r)*36 + tx + 16 + s];
        }
#pragma unroll
        for (int k = 0; k < 9; k++) {
            const ulonglong2* wr = (const ulonglong2*)&wsm[(c*KK + k)*28];
            u64 xa2, xb2;
            DUP2(xa2, xA[k]);
            DUP2(xb2, xB[k]);
#pragma unroll
            for (int q = 0; q < 7; q++) {
                ulonglong2 t = wr[q];
                FMA2(accA[2*q  ], xa2, t.x, accA[2*q  ]);
                FMA2(accA[2*q+1], xa2, t.y, accA[2*q+1]);
                FMA2(accB[2*q  ], xb2, t.x, accB[2*q  ]);
                FMA2(accB[2*q+1], xb2, t.y, accB[2*q+1]);
            }
        }
    }

    float aA[28], aB[28];
#pragma unroll
    for (int p = 0; p < 14; p++) {
        UNPK2(aA[2*p], aA[2*p+1], accA[p]);
        UNPK2(aB[2*p], aB[2*p+1], accB[p]);
    }

    const int pixA = gy*WW + gxA;
    const int pixB = gy*WW + gxB;
#pragma unroll
    for (int o = 0; o < 18; o++) {
        float bo = off_b[o];
        g_offset[(b*18 + o)*HW + pixA] = aA[o] + bo;
        g_offset[(b*18 + o)*HW + pixB] = aB[o] + bo;
    }
#pragma unroll
    for (int o = 0; o < 9; o++) {
        float bo = mod_b[o];
        g_mask[(b*9 + o)*HW + pixA] = 2.f / (1.f + expf(-(aA[18+o] + bo)));
        g_mask[(b*9 + o)*HW + pixB] = 2.f / (1.f + expf(-(aB[18+o] + bo)));
    }
}

// ---------------- kernel 2: deform sample + einsum + BN partial sums ------
// grid (128 rows, 8 batch), block 512. One block = one output row.
// Warp tile: 8 out-ch x 64 px. Accumulators paired over adjacent out-ch, so
// packed f32x2 weight operands come straight from broadcast LDS.128 (no DUP).
#define SMEM2_FLOATS (576*COUT + 2*9*128)
__global__ __launch_bounds__(512) void k_deform(
    const float* __restrict__ x,
    const float* __restrict__ bias,
    float* __restrict__ out)
{
    extern __shared__ float sm[];
    float* Wsm = sm;                 // [c*9+k][64]  (transposed, from g_Wt)
    float* vsm = sm + 576*COUT;      // [2][9][128]

    const int tid  = threadIdx.x;
    const int y    = blockIdx.x;
    const int b    = blockIdx.y;
    const int warp = tid >> 5, lane = tid & 31;
    const int obase = (warp >> 1) * 8;        // 8 oc-groups
    const int px2   = (warp & 1) * 64 + lane*2; // 2 px per lane, 64 px per half

    // stage transposed W coalesced (conflict-free: consecutive words)
    {
        const float4* src = (const float4*)g_Wt;
        float4* dst = (float4*)Wsm;
        for (int i = tid; i < 576*COUT/4; i += 512) dst[i] = src[i];
    }

    // precompute my bilinear samples (channel-independent), tid-indexed
    int   sidx[3][4];
    float swt[3][4];
    int   sk[3], spx[3];
    bool  sval[3];
#pragma unroll
    for (int i = 0; i < 3; i++) {
        int sid = tid + 512*i;
        sval[i] = (sid < 1152);
        int k  = sval[i] ? (sid >> 7) : 0;
        int px = sid & 127;
        sk[i] = k; spx[i] = px;
        float dy = g_offset[(b*18 + 2*k  )*HW + y*WW + px];
        float dx = g_offset[(b*18 + 2*k+1)*HW + y*WW + px];
        float m  = g_mask  [(b*9  + k    )*HW + y*WW + px];
        if (!sval[i]) m = 0.f;
        float py  = dy + (float)(k/3 - 1) + (float)y;
        float pxf = dx + (float)(k - (k/3)*3 - 1) + (float)px;
        float fy = floorf(py), fx = floorf(pxf);
        float ly = py - fy, lx = pxf - fx;
        int y0 = (int)fy, x0 = (int)fx;
        int y1 = y0 + 1,  x1 = x0 + 1;
        float cw[4] = { (1.f-ly)*(1.f-lx)*m, (1.f-ly)*lx*m,
                        ly*(1.f-lx)*m,       ly*lx*m };
        int cy[4] = { y0, y0, y1, y1 };
        int cx[4] = { x0, x1, x0, x1 };
#pragma unroll
        for (int j = 0; j < 4; j++) {
            bool v = (cy[j] >= 0 && cy[j] < HH && cx[j] >= 0 && cx[j] < WW);
            int yc = min(max(cy[j], 0), HH-1);
            int xc = min(max(cx[j], 0), WW-1);
            sidx[i][j] = yc*WW + xc;
            swt[i][j]  = v ? cw[j] : 0.f;
        }
    }

    const float* xb = x + (size_t)b*CIN*HW;

    // gather c=0
    float gv[3][4];
#pragma unroll
    for (int i = 0; i < 3; i++)
#pragma unroll
        for (int j = 0; j < 4; j++) gv[i][j] = xb[sidx[i][j]];

    __syncthreads();   // W staged
#pragma unroll
    for (int i = 0; i < 3; i++) if (sval[i]) {
        float v = gv[i][0]*swt[i][0] + gv[i][1]*swt[i][1]
                + gv[i][2]*swt[i][2] + gv[i][3]*swt[i][3];
        vsm[(0*9 + sk[i])*128 + spx[i]] = v;
    }
    __syncthreads();

    // acc2[p][j]: oc pair (obase+2p, obase+2p+1), pixel j of 2
    u64 acc2[4][2];
#pragma unroll
    for (int p = 0; p < 4; p++) { acc2[p][0] = 0ull; acc2[p][1] = 0ull; }

    for (int c = 0; c < CIN; c++) {
        const int cur = c & 1, nxt = cur ^ 1;

        // issue gather loads for c+1 early (hidden under compute)
        if (c + 1 < CIN) {
            const float* xp = xb + (c+1)*HW;
#pragma unroll
            for (int i = 0; i < 3; i++)
#pragma unroll
                for (int j = 0; j < 4; j++) gv[i][j] = xp[sidx[i][j]];
        }

        // compute: acc[ocpair][px] += v[k][px] * W[ck][ocpair]
#pragma unroll
        for (int k = 0; k < 9; k++) {
            float2 vf = *(const float2*)&vsm[(cur*9 + k)*128 + px2];
            u64 va, vb;
            DUP2(va, vf.x);
            DUP2(vb, vf.y);
            const ulonglong2* wp = (const ulonglong2*)&Wsm[(c*9 + k)*COUT + obase];
            ulonglong2 wA = wp[0];   // oc pairs 0,1
            ulonglong2 wB = wp[1];   // oc pairs 2,3
            FMA2(acc2[0][0], wA.x, va, acc2[0][0]);
            FMA2(acc2[0][1], wA.x, vb, acc2[0][1]);
            FMA2(acc2[1][0], wA.y, va, acc2[1][0]);
            FMA2(acc2[1][1], wA.y, vb, acc2[1][1]);
            FMA2(acc2[2][0], wB.x, va, acc2[2][0]);
            FMA2(acc2[2][1], wB.x, vb, acc2[2][1]);
            FMA2(acc2[3][0], wB.y, va, acc2[3][0]);
            FMA2(acc2[3][1], wB.y, vb, acc2[3][1]);
        }

        if (c + 1 < CIN) {
#pragma unroll
            for (int i = 0; i < 3; i++) if (sval[i]) {
                float v = gv[i][0]*swt[i][0] + gv[i][1]*swt[i][1]
                        + gv[i][2]*swt[i][2] + gv[i][3]*swt[i][3];
                vsm[(nxt*9 + sk[i])*128 + spx[i]] = v;
            }
        }
        __syncthreads();
    }

    // epilogue: bias, write y, per-channel partial sums
#pragma unroll
    for (int p = 0; p < 4; p++) {
        int oc0 = obase + 2*p, oc1 = oc0 + 1;
        float a0e, a0o, a1e, a1o;
        UNPK2(a0e, a0o, acc2[p][0]);   // (oc0,oc1) @ px2
        UNPK2(a1e, a1o, acc2[p][1]);   // (oc0,oc1) @ px2+1
        float b0 = bias[oc0], b1 = bias[oc1];
        float r00 = a0e + b0, r01 = a1e + b0;
        float r10 = a0o + b1, r11 = a1o + b1;
        float2 w0 = make_float2(r00, r01);
        float2 w1 = make_float2(r10, r11);
        *(float2*)&out[(size_t)(b*COUT + oc0)*HW + y*WW + px2] = w0;
        *(float2*)&out[(size_t)(b*COUT + oc1)*HW + y*WW + px2] = w1;

        float s0 = r00 + r01, q0 = r00*r00 + r01*r01;
        float s1 = r10 + r11, q1 = r10*r10 + r11*r11;
#pragma unroll
        for (int d = 16; d; d >>= 1) {
            s0 += __shfl_xor_sync(0xffffffffu, s0, d);
            q0 += __shfl_xor_sync(0xffffffffu, q0, d);
            s1 += __shfl_xor_sync(0xffffffffu, s1, d);
            q1 += __shfl_xor_sync(0xffffffffu, q1, d);
        }
        if (lane == 0) {
            atomicAdd(&g_sum[oc0], s0);
            atomicAdd(&g_sumsq[oc0], q0);
            atomicAdd(&g_sum[oc1], s1);
            atomicAdd(&g_sumsq[oc1], q1);
        }
    }
}

// ---------------- kernel 3: BN finalize ----------------
__global__ void k_bnstats(const float* __restrict__ gamma, const float* __restrict__ beta) {
    int o = threadIdx.x;
    if (o < COUT) {
        const float n = (float)(BB*HW);
        float mean = g_sum[o] / n;
        float var  = g_sumsq[o] / n - mean*mean;
        var = fmaxf(var, 0.f);
        float sc = gamma[o] / sqrtf(var + 1e-5f);
        g_scale[o] = sc;
        g_shift[o] = beta[o] - mean*sc;
    }
}

// ---------------- kernel 4: normalize + relu, in place ----------------
__global__ void k_apply(float* __restrict__ out) {
    int i = blockIdx.x*blockDim.x + threadIdx.x;   // float4 index
    const int total = BB*COUT*HW/4;
    if (i < total) {
        int o = (i >> 12) & 63;   // 4096 float4 per channel plane
        float sc = g_scale[o], sh = g_shift[o];
        float4 v = ((float4*)out)[i];
        v.x = fmaxf(fmaf(v.x, sc, sh), 0.f);
        v.y = fmaxf(fmaf(v.y, sc, sh), 0.f);
        v.z = fmaxf(fmaf(v.z, sc, sh), 0.f);
        v.w = fmaxf(fmaf(v.w, sc, sh), 0.f);
        ((float4*)out)[i] = v;
    }
}

// ---------------- launcher ----------------
extern "C" void kernel_launch(void* const* d_in, const int* in_sizes, int n_in,
                              void* d_out, int out_size)
{
    const float* x     = (const float*)d_in[0];
    const float* off_w = (const float*)d_in[1];
    const float* off_b = (const float*)d_in[2];
    const float* mod_w = (const float*)d_in[3];
    const float* mod_b = (const float*)d_in[4];
    const float* w     = (const float*)d_in[5];
    const float* bias  = (const float*)d_in[6];
    const float* gamma = (const float*)d_in[7];
    const float* beta  = (const float*)d_in[8];
    float* out = (float*)d_out;

    const int smem1 = SMEM1_FLOATS * 4;
    const int smem2 = SMEM2_FLOATS * 4;
    cudaFuncSetAttribute(k_offmask, cudaFuncAttributeMaxDynamicSharedMemorySize, smem1);
    cudaFuncSetAttribute(k_deform,  cudaFuncAttributeMaxDynamicSharedMemorySize, smem2);

    k_zero<<<1, 64>>>();
    k_wprep<<<(COUT*576 + 255)/256, 256>>>(w);
    k_offmask<<<dim3(4,8,8), 256, smem1>>>(x, off_w, off_b, mod_w, mod_b);
    k_deform<<<dim3(128,8), 512, smem2>>>(x, bias, out);
    k_bnstats<<<1, 64>>>(gamma, beta);
    k_apply<<<8192, 256>>>(out);
}

// round 9
// speedup vs baseline: 1.5550x; 1.3696x over previous
#include <cuda_runtime.h>

#define BB 8
#define CIN 64
#define COUT 64
#define HH 128
#define WW 128
#define HW (HH*WW)
#define KK 9
#define CK 576          // CIN*KK

typedef unsigned long long u64;

// packed f32x2 FMA: one FFMA2 SASS inst (2 fp32 FMAs, rt=2/SMSP like FFMA)
#define FMA2(d, a, b, c) \
    asm("fma.rn.f32x2 %0, %1, %2, %3;" : "=l"(d) : "l"(a), "l"(b), "l"(c))
#define DUP2(d, s) \
    asm("mov.b64 %0, {%1, %1};" : "=l"(d) : "r"(__float_as_uint(s)))
#define UNPK2(lo, hi, v) \
    asm("mov.b64 {%0, %1}, %2;" : "=f"(lo), "=f"(hi) : "l"(v))

__device__ __forceinline__ void cp16(void* smem, const void* g) {
    unsigned s = (unsigned)__cvta_generic_to_shared(smem);
    asm volatile("cp.async.cg.shared.global [%0], [%1], 16;" :: "r"(s), "l"(g));
}
#define CP_COMMIT() asm volatile("cp.async.commit_group;")
#define CP_WAIT1()  asm volatile("cp.async.wait_group 1;")
#define CP_WAIT0()  asm volatile("cp.async.wait_group 0;")

// ---------------- scratch (no allocations allowed) ----------------
__device__ float g_offset[BB*18*HW];   // [b][2k+{dy,dx}][h][w]
__device__ float g_mask[BB*9*HW];      // [b][k][h][w]
__device__ float g_Wt2[CK*COUT];       // [k*64+c][o]
__device__ float g_v[(size_t)BB*CK*HW];// [b][k*64+c][h][w]  (302 MB)
__device__ float g_sum[COUT];
__device__ float g_sumsq[COUT];
__device__ float g_scale[COUT];
__device__ float g_shift[COUT];

// ---------------- kernel: zero stats ----------------
__global__ void k_zero() {
    int t = threadIdx.x;
    if (t < COUT) { g_sum[t] = 0.f; g_sumsq[t] = 0.f; }
}

// ---------------- kernel: transpose W -> g_Wt2[(k*64+c)][o] ----------------
__global__ void k_wprep(const float* __restrict__ w) {
    int i = blockIdx.x*256 + threadIdx.x;
    if (i < COUT*CK) {
        int o = i / CK, rem = i - o*CK;      // rem = c*9+k
        int c = rem / KK, k = rem - c*KK;
        g_Wt2[(k*CIN + c)*COUT + o] = w[i];
    }
}

// ---------------- kernel 1: offset (18ch) + mask (9ch) 3x3 conv, fused ----
// grid (4,8,8), block 256 = 16x16 threads, each thread 2 px (cols tx, tx+16)
#define SMEM1_FLOATS (CIN*KK*28 + 18*36)
__global__ __launch_bounds__(256) void k_offmask(
    const float* __restrict__ x,
    const float* __restrict__ off_w, const float* __restrict__ off_b,
    const float* __restrict__ mod_w, const float* __restrict__ mod_b)
{
    extern __shared__ float sm[];
    float* wsm = sm;                  // [c*9+k][28] (27 outputs + 1 zero pad)
    float* xs  = sm + CIN*KK*28;      // [18][36] (34 used cols)

    const int tid = threadIdx.x;
    const int b = blockIdx.z;
    const int ty = tid >> 4, tx = tid & 15;
    const int gy  = blockIdx.y*16 + ty;
    const int gxA = blockIdx.x*32 + tx;
    const int gxB = gxA + 16;

    for (int idx = tid; idx < 28*CIN*KK; idx += 256) {
        int o = idx / (CIN*KK);
        int rem = idx - o*(CIN*KK);
        int c = rem / KK, k = rem - c*KK;
        float v = 0.f;
        if (o < 18)      v = off_w[(o*CIN + c)*KK + k];
        else if (o < 27) v = mod_w[((o-18)*CIN + c)*KK + k];
        wsm[(c*KK + k)*28 + o] = v;
    }

    u64 accA[14], accB[14];
#pragma unroll
    for (int p = 0; p < 14; p++) { accA[p] = 0ull; accB[p] = 0ull; }

    const int gy0 = blockIdx.y*16 - 1;
    const int gx0 = blockIdx.x*32 - 1;

    for (int c = 0; c < CIN; c++) {
        __syncthreads();
        const float* xp = x + (size_t)(b*CIN + c)*HW;
        for (int idx = tid; idx < 18*34; idx += 256) {
            int r = idx / 34, cc = idx - r*34;
            int yy = gy0 + r, xx = gx0 + cc;
            float v = 0.f;
            if (yy >= 0 && yy < HH && xx >= 0 && xx < WW) v = xp[yy*WW + xx];
            xs[r*36 + cc] = v;
        }
        __syncthreads();
        float xA[9], xB[9];
#pragma unroll
        for (int k = 0; k < 9; k++) {
            int r = k/3, s = k - r*3;
            xA[k] = xs[(ty + r)*36 + tx + s];
            xB[k] = xs[(ty + r)*36 + tx + 16 + s];
        }
#pragma unroll
        for (int k = 0; k < 9; k++) {
            const ulonglong2* wr = (const ulonglong2*)&wsm[(c*KK + k)*28];
            u64 xa2, xb2;
            DUP2(xa2, xA[k]);
            DUP2(xb2, xB[k]);
#pragma unroll
            for (int q = 0; q < 7; q++) {
                ulonglong2 t = wr[q];
                FMA2(accA[2*q  ], xa2, t.x, accA[2*q  ]);
                FMA2(accA[2*q+1], xa2, t.y, accA[2*q+1]);
                FMA2(accB[2*q  ], xb2, t.x, accB[2*q  ]);
                FMA2(accB[2*q+1], xb2, t.y, accB[2*q+1]);
            }
        }
    }

    float aA[28], aB[28];
#pragma unroll
    for (int p = 0; p < 14; p++) {
        UNPK2(aA[2*p], aA[2*p+1], accA[p]);
        UNPK2(aB[2*p], aB[2*p+1], accB[p]);
    }

    const int pixA = gy*WW + gxA;
    const int pixB = gy*WW + gxB;
#pragma unroll
    for (int o = 0; o < 18; o++) {
        float bo = off_b[o];
        g_offset[(b*18 + o)*HW + pixA] = aA[o] + bo;
        g_offset[(b*18 + o)*HW + pixB] = aB[o] + bo;
    }
#pragma unroll
    for (int o = 0; o < 9; o++) {
        float bo = mod_b[o];
        g_mask[(b*9 + o)*HW + pixA] = 2.f / (1.f + expf(-(aA[18+o] + bo)));
        g_mask[(b*9 + o)*HW + pixB] = 2.f / (1.f + expf(-(aB[18+o] + bo)));
    }
}

// ---------------- kernel 2a/2b: bilinear sampler -> g_v ------------------
// grid (32, 8, nz), block 512 = 4 rows x 128 px, one k per blockIdx.z.
// Streaming: no smem, no barriers; c-loop unrolled x2 (8 LDG in flight).
__global__ __launch_bounds__(512) void k_sample(const float* __restrict__ x, int k0)
{
    const int tid = threadIdx.x;
    const int px  = tid & 127;
    const int y   = blockIdx.x*4 + (tid >> 7);
    const int b   = blockIdx.y;
    const int k   = k0 + blockIdx.z;
    const int pix = y*WW + px;

    float dy = g_offset[(b*18 + 2*k  )*HW + pix];
    float dx = g_offset[(b*18 + 2*k+1)*HW + pix];
    float m  = g_mask  [(b*9  + k    )*HW + pix];

    float py  = dy + (float)(k/3 - 1) + (float)y;
    float pxf = dx + (float)(k - (k/3)*3 - 1) + (float)px;
    float fy = floorf(py), fx = floorf(pxf);
    float ly = py - fy, lx = pxf - fx;
    int y0 = (int)fy, x0 = (int)fx;
    int y1 = y0 + 1,  x1 = x0 + 1;
    float cw[4] = { (1.f-ly)*(1.f-lx)*m, (1.f-ly)*lx*m,
                    ly*(1.f-lx)*m,       ly*lx*m };
    int cy[4] = { y0, y0, y1, y1 };
    int cx[4] = { x0, x1, x0, x1 };
    int   idx[4];
    float wt[4];
#pragma unroll
    for (int j = 0; j < 4; j++) {
        bool v = (cy[j] >= 0 && cy[j] < HH && cx[j] >= 0 && cx[j] < WW);
        int yc = min(max(cy[j], 0), HH-1);
        int xc = min(max(cx[j], 0), WW-1);
        idx[j] = yc*WW + xc;
        wt[j]  = v ? cw[j] : 0.f;
    }

    const float* xb = x + (size_t)b*CIN*HW;
    float* vp = g_v + ((size_t)(b*CK + k*CIN))*HW + pix;

    for (int c = 0; c < CIN; c += 2) {
        const float* p0 = xb + (size_t)c*HW;
        const float* p1 = p0 + HW;
        float a0 = p0[idx[0]], a1 = p0[idx[1]], a2 = p0[idx[2]], a3 = p0[idx[3]];
        float b0 = p1[idx[0]], b1 = p1[idx[1]], b2 = p1[idx[2]], b3 = p1[idx[3]];
        float v0 = a0*wt[0] + a1*wt[1] + a2*wt[2] + a3*wt[3];
        float v1 = b0*wt[0] + b1*wt[1] + b2*wt[2] + b3*wt[3];
        vp[(size_t)c*HW]     = v0;
        vp[(size_t)(c+1)*HW] = v1;
    }
}

// ---------------- kernel 3: GEMM  out[b,o,:] = Wt2^T @ v[b] + bias --------
// grid (128 px-tiles, 8 batch), block 256 = 8 warps. Warp = 8 oc x 128 px.
// Thread = 8 oc x 4 px; acc paired over adjacent oc (native u64 from LDS.128).
// KC=64 double-buffered via cp.async; 96KB smem -> 2 blocks/SM.
#define KC 64
#define SMEMG_FLOATS (2*KC*128 + 2*KC*64)
__global__ __launch_bounds__(256) void k_gemm(
    const float* __restrict__ bias, float* __restrict__ out)
{
    extern __shared__ float sm[];
    float* Vs = sm;               // [2][KC][128]
    float* Ws = sm + 2*KC*128;    // [2][KC][64]

    const int tid  = threadIdx.x;
    const int warp = tid >> 5, lane = tid & 31;
    const int pxt  = blockIdx.x;          // 128-px tile
    const int b    = blockIdx.y;
    const int oc0  = warp * 8;
    const int pxl  = lane * 4;

    const float* vsrc = g_v + (size_t)b*CK*HW + pxt*128;

    // chunk loader (cp.async, 16B units)
    auto load_chunk = [&](int buf, int ck0) {
        float* vd = &Vs[buf*KC*128];
        for (int i = tid; i < KC*32; i += 256) {
            int r = i >> 5, cc = (i & 31) * 4;
            cp16(&vd[r*128 + cc], vsrc + (size_t)(ck0 + r)*HW + cc);
        }
        float* wd = &Ws[buf*KC*64];
        for (int i = tid; i < KC*16; i += 256) {
            int r = i >> 4, cc = (i & 15) * 4;
            cp16(&wd[r*64 + cc], g_Wt2 + (ck0 + r)*64 + cc);
        }
    };

    u64 acc2[4][4];   // [oc pair][px]
#pragma unroll
    for (int p = 0; p < 4; p++)
#pragma unroll
        for (int j = 0; j < 4; j++) acc2[p][j] = 0ull;

    load_chunk(0, 0);
    CP_COMMIT();

    const int NCH = CK / KC;   // 9
    for (int ch = 0; ch < NCH; ch++) {
        if (ch + 1 < NCH) { load_chunk((ch+1) & 1, (ch+1)*KC); CP_COMMIT(); }
        if (ch + 1 < NCH) { CP_WAIT1(); } else { CP_WAIT0(); }
        __syncthreads();

        const float* Vb = &Vs[(ch & 1)*KC*128];
        const float* Wb = &Ws[(ch & 1)*KC*64];
#pragma unroll 16
        for (int k = 0; k < KC; k++) {
            float4 vf = *(const float4*)&Vb[k*128 + pxl];
            u64 v0, v1, v2, v3;
            DUP2(v0, vf.x); DUP2(v1, vf.y); DUP2(v2, vf.z); DUP2(v3, vf.w);
            const ulonglong2* wp = (const ulonglong2*)&Wb[k*64 + oc0];
            ulonglong2 wA = wp[0];   // oc pairs 0,1
            ulonglong2 wB = wp[1];   // oc pairs 2,3
            FMA2(acc2[0][0], wA.x, v0, acc2[0][0]);
            FMA2(acc2[0][1], wA.x, v1, acc2[0][1]);
            FMA2(acc2[0][2], wA.x, v2, acc2[0][2]);
            FMA2(acc2[0][3], wA.x, v3, acc2[0][3]);
            FMA2(acc2[1][0], wA.y, v0, acc2[1][0]);
            FMA2(acc2[1][1], wA.y, v1, acc2[1][1]);
            FMA2(acc2[1][2], wA.y, v2, acc2[1][2]);
            FMA2(acc2[1][3], wA.y, v3, acc2[1][3]);
            FMA2(acc2[2][0], wB.x, v0, acc2[2][0]);
            FMA2(acc2[2][1], wB.x, v1, acc2[2][1]);
            FMA2(acc2[2][2], wB.x, v2, acc2[2][2]);
            FMA2(acc2[2][3], wB.x, v3, acc2[2][3]);
            FMA2(acc2[3][0], wB.y, v0, acc2[3][0]);
            FMA2(acc2[3][1], wB.y, v1, acc2[3][1]);
            FMA2(acc2[3][2], wB.y, v2, acc2[3][2]);
            FMA2(acc2[3][3], wB.y, v3, acc2[3][3]);
        }
        __syncthreads();
    }

    // epilogue: bias, store, BN partial sums
#pragma unroll
    for (int p = 0; p < 4; p++) {
        int a = oc0 + 2*p, bo = a + 1;
        float e0,o0,e1,o1,e2,o2,e3,o3;
        UNPK2(e0, o0, acc2[p][0]);
        UNPK2(e1, o1, acc2[p][1]);
        UNPK2(e2, o2, acc2[p][2]);
        UNPK2(e3, o3, acc2[p][3]);
        float ba = bias[a], bb = bias[bo];
        float4 ra = make_float4(e0+ba, e1+ba, e2+ba, e3+ba);
        float4 rb = make_float4(o0+bb, o1+bb, o2+bb, o3+bb);
        *(float4*)&out[(size_t)(b*COUT + a )*HW + pxt*128 + pxl] = ra;
        *(float4*)&out[(size_t)(b*COUT + bo)*HW + pxt*128 + pxl] = rb;

        float sa = ra.x+ra.y+ra.z+ra.w;
        float qa = ra.x*ra.x+ra.y*ra.y+ra.z*ra.z+ra.w*ra.w;
        float sb = rb.x+rb.y+rb.z+rb.w;
        float qb = rb.x*rb.x+rb.y*rb.y+rb.z*rb.z+rb.w*rb.w;
#pragma unroll
        for (int d = 16; d; d >>= 1) {
            sa += __shfl_xor_sync(0xffffffffu, sa, d);
            qa += __shfl_xor_sync(0xffffffffu, qa, d);
            sb += __shfl_xor_sync(0xffffffffu, sb, d);
            qb += __shfl_xor_sync(0xffffffffu, qb, d);
        }
        if (lane == 0) {
            atomicAdd(&g_sum[a],  sa);
            atomicAdd(&g_sumsq[a], qa);
            atomicAdd(&g_sum[bo],  sb);
            atomicAdd(&g_sumsq[bo], qb);
        }
    }
}

// ---------------- kernel 4: BN finalize ----------------
__global__ void k_bnstats(const float* __restrict__ gamma, const float* __restrict__ beta) {
    int o = threadIdx.x;
    if (o < COUT) {
        const float n = (float)(BB*HW);
        float mean = g_sum[o] / n;
        float var  = g_sumsq[o] / n - mean*mean;
        var = fmaxf(var, 0.f);
        float sc = gamma[o] / sqrtf(var + 1e-5f);
        g_scale[o] = sc;
        g_shift[o] = beta[o] - mean*sc;
    }
}

// ---------------- kernel 5: normalize + relu, in place ----------------
__global__ void k_apply(float* __restrict__ out) {
    int i = blockIdx.x*blockDim.x + threadIdx.x;   // float4 index
    const int total = BB*COUT*HW/4;
    if (i < total) {
        int o = (i >> 12) & 63;
        float sc = g_scale[o], sh = g_shift[o];
        float4 v = ((float4*)out)[i];
        v.x = fmaxf(fmaf(v.x, sc, sh), 0.f);
        v.y = fmaxf(fmaf(v.y, sc, sh), 0.f);
        v.z = fmaxf(fmaf(v.z, sc, sh), 0.f);
        v.w = fmaxf(fmaf(v.w, sc, sh), 0.f);
        ((float4*)out)[i] = v;
    }
}

// ---------------- launcher ----------------
extern "C" void kernel_launch(void* const* d_in, const int* in_sizes, int n_in,
                              void* d_out, int out_size)
{
    const float* x     = (const float*)d_in[0];
    const float* off_w = (const float*)d_in[1];
    const float* off_b = (const float*)d_in[2];
    const float* mod_w = (const float*)d_in[3];
    const float* mod_b = (const float*)d_in[4];
    const float* w     = (const float*)d_in[5];
    const float* bias  = (const float*)d_in[6];
    const float* gamma = (const float*)d_in[7];
    const float* beta  = (const float*)d_in[8];
    float* out = (float*)d_out;

    const int smem1 = SMEM1_FLOATS * 4;
    const int smemg = SMEMG_FLOATS * 4;
    cudaFuncSetAttribute(k_offmask, cudaFuncAttributeMaxDynamicSharedMemorySize, smem1);
    cudaFuncSetAttribute(k_gemm,    cudaFuncAttributeMaxDynamicSharedMemorySize, smemg);

    // launch order keeps k_gemm at position 6 for the ncu -s5 -c1 window
    k_zero<<<1, 64>>>();
    k_wprep<<<(COUT*CK + 255)/256, 256>>>(w);
    k_offmask<<<dim3(4,8,8), 256, smem1>>>(x, off_w, off_b, mod_w, mod_b);
    k_sample<<<dim3(32,8,5), 512>>>(x, 0);
    k_sample<<<dim3(32,8,4), 512>>>(x, 5);
    k_gemm<<<dim3(128,8), 256, smemg>>>(bias, out);
    k_bnstats<<<1, 64>>>(gamma, beta);
    k_apply<<<8192, 256>>>(out);
}